// round 14
// baseline (speedup 1.0000x reference)
#include <cuda_runtime.h>
#include <cstdint>
#include <cstddef>

// ============================================================================
// Swarm6502 masked 5-expert MoE. R14 = R13 with gemm2 v7:
//  - BK=32, 2-stage double buffer -> 16 barriers (was 32), ~1100cyc cover/chunk
// Pipeline: compact(+cvtB) -> precompute_T -> h -> gemm2 -> flag -> reset
// ============================================================================

#define NTOK 65536
#define HDIM 512
#define OUTW 1296
#define BK   32
#define ASP  36    // As row stride: bank=(36m+k)%32=(4m+k)%32 bijective per warp
#define BSP  72    // Bs row stride: conflict-free b-frag LDS
#define NSTG 2

__device__ int   g_counts[5];                        // zero-init at load
__device__ int   g_lists[5][NTOK];
__device__ float g_H[(size_t)NTOK * HDIM];           // tf32-rounded hidden
__device__ float g_T[(size_t)5 * 6 * 256 * HDIM];    // lookup tables
__device__ float g_Btf[5 * HDIM * 256];              // tf32-rounded B matrices

// index source codes: 0=A 1=X 2=Y 3=SP 4=P 5=PCH 6=PCL 7=Op 8=Val 9=carry(P&1)
__constant__ int c_code[5][6] = {
    {0, 8, 9, 7, -1, -1},   // alu
    {0, 8, 9, 7, -1, -1},   // logic
    {0, 1, 2, 8, 7, -1},    // move
    {5, 6, 4, 8, 3, 7},     // flow
    {0, 1, 3, 4, 8, 7}      // stack
};
__constant__ int c_k[5]    = {4, 4, 5, 6, 6};
__constant__ int c_nout[5] = {264, 264, 256, 256, 256};
__constant__ int c_seg[5]  = {0, 264, 528, 784, 1040};

struct PTP { const float* emb[5]; const float* W1[5]; };
struct HP  { const int* base[9]; const float* b1[5]; };
struct FP  { const float* Wf[2]; float* out; };
struct CP  { const float* B[5]; };
struct G2P { float* out; };

__device__ __forceinline__ float gelu_tanh(float x) {
    float x3 = x * x * x;
    float t  = tanhf(0.7978845608028654f * (x + 0.044715f * x3));
    return 0.5f * x * (1.0f + t);
}
__device__ __forceinline__ uint32_t f2tf32(float x) {
    uint32_t r;
    asm("cvt.rna.tf32.f32 %0, %1;" : "=r"(r) : "f"(x));
    return r;
}
__device__ __forceinline__ void mma_tf32(float* c, const uint32_t* a,
                                         const uint32_t* b) {
    asm volatile(
        "mma.sync.aligned.m16n8k8.row.col.f32.tf32.tf32.f32 "
        "{%0,%1,%2,%3}, {%4,%5,%6,%7}, {%8,%9}, {%0,%1,%2,%3};"
        : "+f"(c[0]), "+f"(c[1]), "+f"(c[2]), "+f"(c[3])
        : "r"(a[0]), "r"(a[1]), "r"(a[2]), "r"(a[3]), "r"(b[0]), "r"(b[1]));
}
#define CP_ASYNC_CG(dst, src, sz) \
    asm volatile("cp.async.cg.shared.global [%0], [%1], 16, %2;" \
                 :: "r"(dst), "l"(src), "r"(sz))
#define CP_COMMIT() asm volatile("cp.async.commit_group;")
#define CP_WAIT1()  asm volatile("cp.async.wait_group 1;")

// ---------------- compact + cvtB (one launch; counts zero on entry) -------------
__global__ void compact_kernel(const int* __restrict__ Op,
                               const int* __restrict__ fu_map, CP p) {
    long gid = (long)blockIdx.x * blockDim.x + threadIdx.x;
    if (gid < NTOK) {
        int e   = fu_map[Op[gid]];
        int pos = atomicAdd(&g_counts[e], 1);
        g_lists[e][pos] = (int)gid;
    } else {
        long i = gid - NTOK;                 // 0 .. 5*131072-1
        if (i < 5L * HDIM * 256) {
            int e = (int)(i >> 17);
            int r = (int)(i & (HDIM * 256 - 1));
            g_Btf[i] = __uint_as_float(f2tf32(__ldg(p.B[e] + r)));
        }
    }
}
__global__ void reset_counts() {
    if (threadIdx.x < 5) g_counts[threadIdx.x] = 0;
}

// ---------------- precompute T[e][j] = emb_ej @ W1_ej ---------------------------
#define PT_SMEM ((64 * 65 + 64 * 128) * 4)
__global__ void __launch_bounds__(256) precompute_T(PTP p) {
    int z = blockIdx.z, e = z / 6, j = z % 6;
    if (j >= c_k[e]) return;
    int v0 = blockIdx.x * 64;
    int n0 = blockIdx.y * 128;

    extern __shared__ float smp[];
    float (*Es)[65]  = (float(*)[65])smp;
    float (*Ws)[128] = (float(*)[128])(smp + 64 * 65);
    int tid = threadIdx.x;

    {
        int r = tid >> 2, c = (tid & 3) * 16;
        const float* src = p.emb[e] + ((size_t)j * 256 + v0 + r) * 64 + c;
#pragma unroll
        for (int q = 0; q < 16; q++) Es[r][c + q] = __ldg(src + q);
    }
    {
        int r = tid >> 2, c0 = (tid & 3) * 32;
        const float4* src =
            (const float4*)(p.W1[e] + ((size_t)(j * 64 + r)) * HDIM + n0 + c0);
        float4* dst = (float4*)&Ws[r][c0];
#pragma unroll
        for (int q = 0; q < 8; q++) dst[q] = __ldg(src + q);
    }
    __syncthreads();

    float acc[4][8];
#pragma unroll
    for (int i = 0; i < 4; i++)
#pragma unroll
        for (int jj = 0; jj < 8; jj++) acc[i][jj] = 0.f;

    int tm = (tid >> 4) * 4, tn = (tid & 15) * 8;
#pragma unroll
    for (int k = 0; k < 64; k++) {
        float a[4], b[8];
#pragma unroll
        for (int i = 0; i < 4; i++) a[i] = Es[tm + i][k];
        float4 b0 = *(const float4*)&Ws[k][tn];
        float4 b1 = *(const float4*)&Ws[k][tn + 4];
        b[0] = b0.x; b[1] = b0.y; b[2] = b0.z; b[3] = b0.w;
        b[4] = b1.x; b[5] = b1.y; b[6] = b1.z; b[7] = b1.w;
#pragma unroll
        for (int i = 0; i < 4; i++)
#pragma unroll
            for (int jj = 0; jj < 8; jj++)
                acc[i][jj] = fmaf(a[i], b[jj], acc[i][jj]);
    }

    float* T = g_T + ((size_t)(e * 6 + j) * 256) * HDIM;
#pragma unroll
    for (int i = 0; i < 4; i++) {
        float* d = T + (size_t)(v0 + tm + i) * HDIM + n0 + tn;
        *(float4*)d       = make_float4(acc[i][0], acc[i][1], acc[i][2], acc[i][3]);
        *(float4*)(d + 4) = make_float4(acc[i][4], acc[i][5], acc[i][6], acc[i][7]);
    }
}

// ---------------- h v2: smem-staged indices -> independent gathers ---------------
__global__ void __launch_bounds__(256) h_kernel(HP p) {
    int e  = blockIdx.y;
    int C  = g_counts[e];
    int m0 = blockIdx.x * 64;
    if (m0 >= C) return;

    __shared__ int s_tok[64];
    __shared__ int s_idx[6][64];

    int tid = threadIdx.x;
    int kc  = c_k[e];
    if (tid < 64) {
        int m = m0 + tid;
        s_tok[tid] = (m < C) ? g_lists[e][m] : -1;
    }
    __syncthreads();
    for (int u = tid; u < kc * 64; u += 256) {
        int j = u >> 6, m = u & 63;
        int tok = s_tok[m];
        int idx = 0;
        if (tok >= 0) {
            int code = c_code[e][j];
            idx = (code == 9) ? (__ldg(p.base[4] + tok) & 1)
                              : __ldg(p.base[code] + tok);
        }
        s_idx[j][m] = idx;
    }
    __syncthreads();

    int g = tid >> 7, t = tid & 127;
    float4 bias = __ldg((const float4*)p.b1[e] + t);
    const float* Tb = g_T + ((size_t)(e * 6) << 17);

    for (int lm = g * 32; lm < g * 32 + 32; lm += 2) {
        int tok0 = s_tok[lm], tok1 = s_tok[lm + 1];
        if (tok0 < 0) continue;
        float4 a0 = bias, a1 = bias;
        for (int j = 0; j < kc; j++) {
            float4 v0 = ((const float4*)(
                Tb + (((size_t)j * 256 + s_idx[j][lm]) << 9)))[t];
            a0.x += v0.x; a0.y += v0.y; a0.z += v0.z; a0.w += v0.w;
            if (tok1 >= 0) {
                float4 v1 = ((const float4*)(
                    Tb + (((size_t)j * 256 + s_idx[j][lm + 1]) << 9)))[t];
                a1.x += v1.x; a1.y += v1.y; a1.z += v1.z; a1.w += v1.w;
            }
        }
        float4 o0;
        o0.x = __uint_as_float(f2tf32(gelu_tanh(a0.x)));
        o0.y = __uint_as_float(f2tf32(gelu_tanh(a0.y)));
        o0.z = __uint_as_float(f2tf32(gelu_tanh(a0.z)));
        o0.w = __uint_as_float(f2tf32(gelu_tanh(a0.w)));
        ((float4*)(g_H + ((size_t)tok0 << 9)))[t] = o0;
        if (tok1 >= 0) {
            float4 o1;
            o1.x = __uint_as_float(f2tf32(gelu_tanh(a1.x)));
            o1.y = __uint_as_float(f2tf32(gelu_tanh(a1.y)));
            o1.z = __uint_as_float(f2tf32(gelu_tanh(a1.z)));
            o1.w = __uint_as_float(f2tf32(gelu_tanh(a1.w)));
            ((float4*)(g_H + ((size_t)tok1 << 9)))[t] = o1;
        }
    }
}

// ---------------- flag cols (alu/logic) ------------------------------------------
__global__ void __launch_bounds__(256) flag_kernel(FP p) {
    int e  = blockIdx.y;
    int C  = g_counts[e];
    int m0 = blockIdx.x * 32;
    if (m0 >= C) return;

    __shared__ float sWf[HDIM][8];
    int tid = threadIdx.x;
    const float4* Wf4 = (const float4*)p.Wf[e];
#pragma unroll
    for (int i = 0; i < 4; i++)
        ((float4*)sWf)[tid + i * 256] = __ldg(Wf4 + tid + i * 256);
    __syncthreads();

    int r = tid >> 3, f = tid & 7;
    int mi = m0 + r;
    if (mi >= C) return;
    int tok = g_lists[e][mi];
    const float4* h = (const float4*)(g_H + ((size_t)tok << 9));
    float dot = 0.f;
#pragma unroll 4
    for (int k4 = 0; k4 < 128; k4++) {
        float4 hv = __ldg(h + k4);
        dot += hv.x * sWf[k4 * 4 + 0][f];
        dot += hv.y * sWf[k4 * 4 + 1][f];
        dot += hv.z * sWf[k4 * 4 + 2][f];
        dot += hv.w * sWf[k4 * 4 + 3][f];
    }
    p.out[(size_t)tok * OUTW + c_seg[e] + 256 + f] = dot;
}

// ---------------- gemm2 v7: BK=32, 2-stage cp.async, distributed zero-fill -------
// (C x 512) @ (512 x 256). BM=128, BN=64, BK=32, 16 chunks, 2 stages, 8 warps.
// warp tile 32x32. grid (4, 512, 5): n0 inner -> A tile L2-shared by 4 blocks.
#define G2_SMEM (NSTG * (128 * ASP + BK * BSP) * 4)
__global__ void __launch_bounds__(256, 3) gemm2_kernel(G2P p) {
    int e  = blockIdx.z;
    int C  = g_counts[e];
    int m0 = blockIdx.y * 128;
    if (m0 >= C) return;
    int n0 = blockIdx.x * 64;

    extern __shared__ uint32_t smg[];
    uint32_t (*As)[ASP] = (uint32_t(*)[ASP])smg;                      // [NSTG*128][ASP]
    uint32_t (*Bs)[BSP] = (uint32_t(*)[BSP])(smg + NSTG * 128 * ASP); // [NSTG*BK][BSP]
    __shared__ int s_tok[128];

    int tid = threadIdx.x;
    if (tid < 128) {
        int m = m0 + tid;
        s_tok[tid] = (m < C) ? g_lists[e][m] : -1;
    }
    __syncthreads();

    // zero-fill complement, distributed across the 4 n-blocks of this m-tile
    {
        int s4 = c_seg[e] >> 2;
        int e4 = (c_seg[e] + c_nout[e]) >> 2;
        float4* out4 = (float4*)p.out;
        float4 z = make_float4(0.f, 0.f, 0.f, 0.f);
        for (int u = tid + (int)blockIdx.x * 256; u < 128 * (OUTW / 4);
             u += 1024) {
            int m = u / (OUTW / 4);
            int f = u - m * (OUTW / 4);
            if (f >= s4 && f < e4) continue;
            int tok = s_tok[m];
            if (tok < 0) continue;
            out4[(size_t)tok * (OUTW / 4) + f] = z;
        }
    }

    // ---- staging assignments (fixed per thread) ----
    // A chunk: 128 rows x 32 k = 1024 float4; 4 per thread (1 row, 16 k)
    int ar  = tid >> 1;              // row 0..127
    int akq = (tid & 1) * 16;        // k offset 0 or 16
    int tokA = s_tok[ar];
    const float* srcA = g_H + ((size_t)(tokA < 0 ? 0 : tokA) << 9) + akq;
    int szA = (tokA < 0) ? 0 : 16;
    // B chunk: 32 k-rows x 64 n = 512 float4; 2 per thread
    int bk = tid >> 4;               // 0..15; rows bk and bk+16
    int bn = (tid & 15) * 4;         // 0..60
    const float* __restrict__ Bg = g_Btf + ((size_t)e * HDIM * 256);

    uint32_t sbase = (uint32_t)__cvta_generic_to_shared(smg);
    const uint32_t BOFF = NSTG * 128 * ASP * 4;   // byte offset of Bs

    auto stage = [&](int st, int cc) {
        int kk = cc * BK;
#pragma unroll
        for (int q = 0; q < 4; q++) {
            uint32_t dA = sbase + ((st * 128 + ar) * ASP + akq + q * 4) * 4;
            CP_ASYNC_CG(dA, srcA + kk + q * 4, szA);
        }
        uint32_t dB0 = sbase + BOFF + ((st * BK + bk) * BSP + bn) * 4;
        uint32_t dB1 = sbase + BOFF + ((st * BK + bk + 16) * BSP + bn) * 4;
        CP_ASYNC_CG(dB0, Bg + (size_t)(kk + bk) * 256 + n0 + bn, 16);
        CP_ASYNC_CG(dB1, Bg + (size_t)(kk + bk + 16) * 256 + n0 + bn, 16);
    };

    int lane = tid & 31, wrp = tid >> 5;
    int wm = (wrp & 3) * 32;
    int wn = (wrp >> 2) * 32;
    int grp = lane >> 2, th4 = lane & 3;

    float c[2][4][4];
#pragma unroll
    for (int mt = 0; mt < 2; mt++)
#pragma unroll
        for (int nt = 0; nt < 4; nt++)
#pragma unroll
            for (int i = 0; i < 4; i++) c[mt][nt][i] = 0.f;

    stage(0, 0); CP_COMMIT();
    stage(1, 1); CP_COMMIT();

    int cur = 0;
    for (int cc = 0; cc < 16; cc++) {
        CP_WAIT1();          // chunk cc landed in buffer cur
        __syncthreads();     // all warps done reading buffer cur^1 (chunk cc-1)

        // refill buffer cur^1 with chunk cc+1... careful: chunk cc+1 is already
        // in flight into buffer cur^1 (staged in iteration cc-1). Stage cc+2
        // into... 2-stage: stage chunk cc+2 would collide with cc+1 in flight.
        // Correct 2-stage: issue stage(cc+2 -> buffer cur) AFTER this
        // iteration's MMA? No: issue cc+2 into buffer cur is wrong (cur holds
        // cc, being read now). Classic order: MMA cc from cur, barrier at TOP
        // of next iter guarantees cc done; so stage cc+2 into cur at the
        // BOTTOM after a barrier. We instead stage at top of iter cc+1:
        if (cc + 1 < 16) {
            // buffer cur^1 holds arriving chunk cc+1; buffer cur is being
            // consumed this iteration. Stage chunk cc+2 only after cc's MMA.
        }

        int ab = cur * 128;
        int bb = cur * BK;
#pragma unroll
        for (int k8 = 0; k8 < BK; k8 += 8) {
            int kb = k8 + th4;
            uint32_t a[2][4], b[4][2];
#pragma unroll
            for (int mt = 0; mt < 2; mt++) {
                int mb = ab + wm + mt * 16;
                a[mt][0] = As[mb + grp][kb];
                a[mt][1] = As[mb + 8 + grp][kb];
                a[mt][2] = As[mb + grp][kb + 4];
                a[mt][3] = As[mb + 8 + grp][kb + 4];
            }
#pragma unroll
            for (int nt = 0; nt < 4; nt++) {
                b[nt][0] = Bs[bb + kb][wn + nt * 8 + grp];
                b[nt][1] = Bs[bb + kb + 4][wn + nt * 8 + grp];
            }
#pragma unroll
            for (int mt = 0; mt < 2; mt++)
#pragma unroll
                for (int nt = 0; nt < 4; nt++)
                    mma_tf32(c[mt][nt], a[mt], b[nt]);
        }

        __syncthreads();     // all warps done with chunk cc (buffer cur)
        if (cc + 2 < 16) {
            stage(cur, cc + 2);   // refill cur with chunk cc+2
        }
        CP_COMMIT();
        cur ^= 1;
    }

    // epilogue
    int seg = c_seg[e];
#pragma unroll
    for (int mt = 0; mt < 2; mt++) {
        int r0   = wm + mt * 16 + grp;
        int tok0 = s_tok[r0];
        int tok1 = s_tok[r0 + 8];
        if (tok0 >= 0) {
            float* o = p.out + (size_t)tok0 * OUTW + seg + n0 + wn + 2 * th4;
#pragma unroll
            for (int nt = 0; nt < 4; nt++)
                *(float2*)(o + nt * 8) = make_float2(c[mt][nt][0], c[mt][nt][1]);
        }
        if (tok1 >= 0) {
            float* o = p.out + (size_t)tok1 * OUTW + seg + n0 + wn + 2 * th4;
#pragma unroll
            for (int nt = 0; nt < 4; nt++)
                *(float2*)(o + nt * 8) = make_float2(c[mt][nt][2], c[mt][nt][3]);
        }
    }
}

// ---------------- host launcher ---------------------------------------------------
extern "C" void kernel_launch(void* const* d_in, const int* in_sizes, int n_in,
                              void* d_out, int out_size) {
    (void)in_sizes; (void)n_in; (void)out_size;
    // input order (setup_inputs dict order):
    // 0:A 1:X 2:Y 3:SP 4:P 5:PCH 6:PCL 7:Op 8:Val 9:fu_map
    // 10..24: (emb, W1, b1) x {alu, logic, move, flow, stack}
    // 25:alu_Wr 26:alu_Wf 27:logic_Wr 28:logic_Wf 29:move_Wo 30:flow_Wo 31:stack_Wo
    cudaFuncSetAttribute(precompute_T,
                         cudaFuncAttributeMaxDynamicSharedMemorySize, PT_SMEM);
    cudaFuncSetAttribute(gemm2_kernel,
                         cudaFuncAttributeMaxDynamicSharedMemorySize, G2_SMEM);

    PTP pt;
    HP  hp;
    for (int i = 0; i < 9; i++) hp.base[i] = (const int*)d_in[i];
    for (int e = 0; e < 5; e++) {
        pt.emb[e] = (const float*)d_in[10 + 3 * e];
        pt.W1[e]  = (const float*)d_in[11 + 3 * e];
        hp.b1[e]  = (const float*)d_in[12 + 3 * e];
    }
    FP fp;
    fp.Wf[0] = (const float*)d_in[26];
    fp.Wf[1] = (const float*)d_in[28];
    fp.out   = (float*)d_out;

    CP cp;
    cp.B[0] = (const float*)d_in[25];
    cp.B[1] = (const float*)d_in[27];
    cp.B[2] = (const float*)d_in[29];
    cp.B[3] = (const float*)d_in[30];
    cp.B[4] = (const float*)d_in[31];

    G2P p2;
    p2.out = (float*)d_out;

    const int* Op = (const int*)d_in[7];
    const int* fu = (const int*)d_in[9];

    int nblk = (NTOK + 5 * HDIM * 256) / 256;                 // compaction + cvtB
    compact_kernel<<<nblk, 256>>>(Op, fu, cp);                // launch 0
    precompute_T<<<dim3(4, 4, 30), 256, PT_SMEM>>>(pt);       // launch 1
    h_kernel<<<dim3(1024, 5), 256>>>(hp);                     // launch 2
    gemm2_kernel<<<dim3(4, 512, 5), 256, G2_SMEM>>>(p2);      // launch 3 (profiled)
    flag_kernel<<<dim3(2048, 2), 256>>>(fp);                  // launch 4
    reset_counts<<<1, 32>>>();                                // launch 5
}

// round 15
// speedup vs baseline: 1.1906x; 1.1906x over previous
#include <cuda_runtime.h>
#include <cstdint>
#include <cstddef>

// ============================================================================
// Swarm6502 masked 5-expert MoE. R15 = R13 gemm2 (revert R14) + flag fusion:
//  - gemm2: BK=16, 4-stage cp.async, distributed zero-fill (R13 exact)
//  - flags (e<2) computed inside gemm2 from the staged A tiles; each of the
//    4 n-blocks handles 2 of 8 flag cols. flag_kernel deleted.
// Pipeline: compact(+cvtB) -> precompute_T -> h -> gemm2 -> reset
// ============================================================================

#define NTOK 65536
#define HDIM 512
#define OUTW 1296
#define BK   16
#define ASP  20    // As row stride: conflict-free a-frag LDS
#define BSP  72    // Bs row stride: conflict-free b-frag LDS
#define NSTG 4

__device__ int   g_counts[5];                        // zero-init at load
__device__ int   g_lists[5][NTOK];
__device__ float g_H[(size_t)NTOK * HDIM];           // tf32-rounded hidden
__device__ float g_T[(size_t)5 * 6 * 256 * HDIM];    // lookup tables
__device__ float g_Btf[5 * HDIM * 256];              // tf32-rounded B matrices

// index source codes: 0=A 1=X 2=Y 3=SP 4=P 5=PCH 6=PCL 7=Op 8=Val 9=carry(P&1)
__constant__ int c_code[5][6] = {
    {0, 8, 9, 7, -1, -1},   // alu
    {0, 8, 9, 7, -1, -1},   // logic
    {0, 1, 2, 8, 7, -1},    // move
    {5, 6, 4, 8, 3, 7},     // flow
    {0, 1, 3, 4, 8, 7}      // stack
};
__constant__ int c_k[5]    = {4, 4, 5, 6, 6};
__constant__ int c_nout[5] = {264, 264, 256, 256, 256};
__constant__ int c_seg[5]  = {0, 264, 528, 784, 1040};

struct PTP { const float* emb[5]; const float* W1[5]; };
struct HP  { const int* base[9]; const float* b1[5]; };
struct CP  { const float* B[5]; };
struct G2P { const float* Wf[2]; float* out; };

__device__ __forceinline__ float gelu_tanh(float x) {
    float x3 = x * x * x;
    float t  = tanhf(0.7978845608028654f * (x + 0.044715f * x3));
    return 0.5f * x * (1.0f + t);
}
__device__ __forceinline__ uint32_t f2tf32(float x) {
    uint32_t r;
    asm("cvt.rna.tf32.f32 %0, %1;" : "=r"(r) : "f"(x));
    return r;
}
__device__ __forceinline__ void mma_tf32(float* c, const uint32_t* a,
                                         const uint32_t* b) {
    asm volatile(
        "mma.sync.aligned.m16n8k8.row.col.f32.tf32.tf32.f32 "
        "{%0,%1,%2,%3}, {%4,%5,%6,%7}, {%8,%9}, {%0,%1,%2,%3};"
        : "+f"(c[0]), "+f"(c[1]), "+f"(c[2]), "+f"(c[3])
        : "r"(a[0]), "r"(a[1]), "r"(a[2]), "r"(a[3]), "r"(b[0]), "r"(b[1]));
}
#define CP_ASYNC_CG(dst, src, sz) \
    asm volatile("cp.async.cg.shared.global [%0], [%1], 16, %2;" \
                 :: "r"(dst), "l"(src), "r"(sz))
#define CP_COMMIT() asm volatile("cp.async.commit_group;")
#define CP_WAIT2()  asm volatile("cp.async.wait_group 2;")

// ---------------- compact + cvtB (one launch; counts zero on entry) -------------
__global__ void compact_kernel(const int* __restrict__ Op,
                               const int* __restrict__ fu_map, CP p) {
    long gid = (long)blockIdx.x * blockDim.x + threadIdx.x;
    if (gid < NTOK) {
        int e   = fu_map[Op[gid]];
        int pos = atomicAdd(&g_counts[e], 1);
        g_lists[e][pos] = (int)gid;
    } else {
        long i = gid - NTOK;                 // 0 .. 5*131072-1
        if (i < 5L * HDIM * 256) {
            int e = (int)(i >> 17);
            int r = (int)(i & (HDIM * 256 - 1));
            g_Btf[i] = __uint_as_float(f2tf32(__ldg(p.B[e] + r)));
        }
    }
}
__global__ void reset_counts() {
    if (threadIdx.x < 5) g_counts[threadIdx.x] = 0;
}

// ---------------- precompute T[e][j] = emb_ej @ W1_ej ---------------------------
#define PT_SMEM ((64 * 65 + 64 * 128) * 4)
__global__ void __launch_bounds__(256) precompute_T(PTP p) {
    int z = blockIdx.z, e = z / 6, j = z % 6;
    if (j >= c_k[e]) return;
    int v0 = blockIdx.x * 64;
    int n0 = blockIdx.y * 128;

    extern __shared__ float smp[];
    float (*Es)[65]  = (float(*)[65])smp;
    float (*Ws)[128] = (float(*)[128])(smp + 64 * 65);
    int tid = threadIdx.x;

    {
        int r = tid >> 2, c = (tid & 3) * 16;
        const float* src = p.emb[e] + ((size_t)j * 256 + v0 + r) * 64 + c;
#pragma unroll
        for (int q = 0; q < 16; q++) Es[r][c + q] = __ldg(src + q);
    }
    {
        int r = tid >> 2, c0 = (tid & 3) * 32;
        const float4* src =
            (const float4*)(p.W1[e] + ((size_t)(j * 64 + r)) * HDIM + n0 + c0);
        float4* dst = (float4*)&Ws[r][c0];
#pragma unroll
        for (int q = 0; q < 8; q++) dst[q] = __ldg(src + q);
    }
    __syncthreads();

    float acc[4][8];
#pragma unroll
    for (int i = 0; i < 4; i++)
#pragma unroll
        for (int jj = 0; jj < 8; jj++) acc[i][jj] = 0.f;

    int tm = (tid >> 4) * 4, tn = (tid & 15) * 8;
#pragma unroll
    for (int k = 0; k < 64; k++) {
        float a[4], b[8];
#pragma unroll
        for (int i = 0; i < 4; i++) a[i] = Es[tm + i][k];
        float4 b0 = *(const float4*)&Ws[k][tn];
        float4 b1 = *(const float4*)&Ws[k][tn + 4];
        b[0] = b0.x; b[1] = b0.y; b[2] = b0.z; b[3] = b0.w;
        b[4] = b1.x; b[5] = b1.y; b[6] = b1.z; b[7] = b1.w;
#pragma unroll
        for (int i = 0; i < 4; i++)
#pragma unroll
            for (int jj = 0; jj < 8; jj++)
                acc[i][jj] = fmaf(a[i], b[jj], acc[i][jj]);
    }

    float* T = g_T + ((size_t)(e * 6 + j) * 256) * HDIM;
#pragma unroll
    for (int i = 0; i < 4; i++) {
        float* d = T + (size_t)(v0 + tm + i) * HDIM + n0 + tn;
        *(float4*)d       = make_float4(acc[i][0], acc[i][1], acc[i][2], acc[i][3]);
        *(float4*)(d + 4) = make_float4(acc[i][4], acc[i][5], acc[i][6], acc[i][7]);
    }
}

// ---------------- h v2: smem-staged indices -> independent gathers ---------------
__global__ void __launch_bounds__(256) h_kernel(HP p) {
    int e  = blockIdx.y;
    int C  = g_counts[e];
    int m0 = blockIdx.x * 64;
    if (m0 >= C) return;

    __shared__ int s_tok[64];
    __shared__ int s_idx[6][64];

    int tid = threadIdx.x;
    int kc  = c_k[e];
    if (tid < 64) {
        int m = m0 + tid;
        s_tok[tid] = (m < C) ? g_lists[e][m] : -1;
    }
    __syncthreads();
    for (int u = tid; u < kc * 64; u += 256) {
        int j = u >> 6, m = u & 63;
        int tok = s_tok[m];
        int idx = 0;
        if (tok >= 0) {
            int code = c_code[e][j];
            idx = (code == 9) ? (__ldg(p.base[4] + tok) & 1)
                              : __ldg(p.base[code] + tok);
        }
        s_idx[j][m] = idx;
    }
    __syncthreads();

    int g = tid >> 7, t = tid & 127;
    float4 bias = __ldg((const float4*)p.b1[e] + t);
    const float* Tb = g_T + ((size_t)(e * 6) << 17);

    for (int lm = g * 32; lm < g * 32 + 32; lm += 2) {
        int tok0 = s_tok[lm], tok1 = s_tok[lm + 1];
        if (tok0 < 0) continue;
        float4 a0 = bias, a1 = bias;
        for (int j = 0; j < kc; j++) {
            float4 v0 = ((const float4*)(
                Tb + (((size_t)j * 256 + s_idx[j][lm]) << 9)))[t];
            a0.x += v0.x; a0.y += v0.y; a0.z += v0.z; a0.w += v0.w;
            if (tok1 >= 0) {
                float4 v1 = ((const float4*)(
                    Tb + (((size_t)j * 256 + s_idx[j][lm + 1]) << 9)))[t];
                a1.x += v1.x; a1.y += v1.y; a1.z += v1.z; a1.w += v1.w;
            }
        }
        float4 o0;
        o0.x = __uint_as_float(f2tf32(gelu_tanh(a0.x)));
        o0.y = __uint_as_float(f2tf32(gelu_tanh(a0.y)));
        o0.z = __uint_as_float(f2tf32(gelu_tanh(a0.z)));
        o0.w = __uint_as_float(f2tf32(gelu_tanh(a0.w)));
        ((float4*)(g_H + ((size_t)tok0 << 9)))[t] = o0;
        if (tok1 >= 0) {
            float4 o1;
            o1.x = __uint_as_float(f2tf32(gelu_tanh(a1.x)));
            o1.y = __uint_as_float(f2tf32(gelu_tanh(a1.y)));
            o1.z = __uint_as_float(f2tf32(gelu_tanh(a1.z)));
            o1.w = __uint_as_float(f2tf32(gelu_tanh(a1.w)));
            ((float4*)(g_H + ((size_t)tok1 << 9)))[t] = o1;
        }
    }
}

// ---------------- gemm2 v8: R13 pipeline + fused flag cols -----------------------
// (C x 512) @ (512 x 256). BM=128, BN=64, BK=16, 32 chunks, 4 stages, 8 warps.
// warp tile 32x32. grid (4, 512, 5): n0 inner -> A tile L2-shared by 4 blocks.
// e<2: block x computes flag cols {2x, 2x+1} from the staged A (1 pair/thread).
#define SWF_OFF (NSTG * (128 * ASP + BK * BSP))        // word offset of sWf
#define G2_SMEM ((SWF_OFF + 512 * 2) * 4)
__global__ void __launch_bounds__(256, 3) gemm2_kernel(G2P p) {
    int e  = blockIdx.z;
    int C  = g_counts[e];
    int m0 = blockIdx.y * 128;
    if (m0 >= C) return;
    int n0 = blockIdx.x * 64;

    extern __shared__ uint32_t smg[];
    uint32_t (*As)[ASP] = (uint32_t(*)[ASP])smg;                      // [NSTG*128][ASP]
    uint32_t (*Bs)[BSP] = (uint32_t(*)[BSP])(smg + NSTG * 128 * ASP); // [NSTG*BK][BSP]
    float (*sWf)[2] = (float(*)[2])(smg + SWF_OFF);                   // [512][2]
    __shared__ int s_tok[128];

    int tid = threadIdx.x;
    if (tid < 128) {
        int m = m0 + tid;
        s_tok[tid] = (m < C) ? g_lists[e][m] : -1;
    }
    bool doFlag = (e < 2);
    int f0 = blockIdx.x * 2;
    if (doFlag) {
        const float* Wf = p.Wf[e];
        for (int u = tid; u < 512; u += 256) {
            sWf[u][0] = __ldg(Wf + u * 8 + f0);
            sWf[u][1] = __ldg(Wf + u * 8 + f0 + 1);
        }
    }
    __syncthreads();

    // zero-fill complement, distributed across the 4 n-blocks of this m-tile
    {
        int s4 = c_seg[e] >> 2;
        int e4 = (c_seg[e] + c_nout[e]) >> 2;
        float4* out4 = (float4*)p.out;
        float4 z = make_float4(0.f, 0.f, 0.f, 0.f);
        for (int u = tid + (int)blockIdx.x * 256; u < 128 * (OUTW / 4);
             u += 1024) {
            int m = u / (OUTW / 4);
            int f = u - m * (OUTW / 4);
            if (f >= s4 && f < e4) continue;
            int tok = s_tok[m];
            if (tok < 0) continue;
            out4[(size_t)tok * (OUTW / 4) + f] = z;
        }
    }

    // ---- staging assignments (fixed per thread) ----
    int ar0 = tid >> 2;              // rows 0..63
    int ar1 = 64 + ar0;              // rows 64..127
    int akq = (tid & 3) * 4;         // k-quad within chunk
    int tokA0 = s_tok[ar0], tokA1 = s_tok[ar1];
    const float* srcA0 = g_H + ((size_t)(tokA0 < 0 ? 0 : tokA0) << 9) + akq;
    const float* srcA1 = g_H + ((size_t)(tokA1 < 0 ? 0 : tokA1) << 9) + akq;
    int szA0 = (tokA0 < 0) ? 0 : 16;
    int szA1 = (tokA1 < 0) ? 0 : 16;
    int bk = tid >> 4;               // 0..15 (B k-row)
    int bn = (tid & 15) * 4;         // 0..60
    const float* __restrict__ Bg = g_Btf + ((size_t)e * HDIM * 256);

    uint32_t sbase = (uint32_t)__cvta_generic_to_shared(smg);
    const uint32_t BOFF = NSTG * 128 * ASP * 4;   // byte offset of Bs

    auto stage = [&](int st, int cc) {
        int kk = cc * BK;
        uint32_t dA0 = sbase + ((st * 128 + ar0) * ASP + akq) * 4;
        uint32_t dA1 = sbase + ((st * 128 + ar1) * ASP + akq) * 4;
        CP_ASYNC_CG(dA0, srcA0 + kk, szA0);
        CP_ASYNC_CG(dA1, srcA1 + kk, szA1);
        uint32_t dB = sbase + BOFF + ((st * BK + bk) * BSP + bn) * 4;
        CP_ASYNC_CG(dB, Bg + (size_t)(kk + bk) * 256 + n0 + bn, 16);
    };

    int lane = tid & 31, wrp = tid >> 5;
    int wm = (wrp & 3) * 32;
    int wn = (wrp >> 2) * 32;
    int grp = lane >> 2, th4 = lane & 3;

    // flag assignment: 1 (token, flag) pair per thread
    int fm = tid >> 1;               // token row 0..127
    int ff = tid & 1;                // 0/1 -> flag col f0+ff
    float fdot = 0.f;

    float c[2][4][4];
#pragma unroll
    for (int mt = 0; mt < 2; mt++)
#pragma unroll
        for (int nt = 0; nt < 4; nt++)
#pragma unroll
            for (int i = 0; i < 4; i++) c[mt][nt][i] = 0.f;

    stage(0, 0); CP_COMMIT();
    stage(1, 1); CP_COMMIT();
    stage(2, 2); CP_COMMIT();

    int cur = 0;
    for (int cc = 0; cc < 32; cc++) {
        CP_WAIT2();
        __syncthreads();

        int ab = cur * 128;
        int bb = cur * BK;
#pragma unroll
        for (int k8 = 0; k8 < BK; k8 += 8) {
            int kb = k8 + th4;
            uint32_t a[2][4], b[4][2];
#pragma unroll
            for (int mt = 0; mt < 2; mt++) {
                int mb = ab + wm + mt * 16;
                a[mt][0] = As[mb + grp][kb];
                a[mt][1] = As[mb + 8 + grp][kb];
                a[mt][2] = As[mb + grp][kb + 4];
                a[mt][3] = As[mb + 8 + grp][kb + 4];
            }
#pragma unroll
            for (int nt = 0; nt < 4; nt++) {
                b[nt][0] = Bs[bb + kb][wn + nt * 8 + grp];
                b[nt][1] = Bs[bb + kb + 4][wn + nt * 8 + grp];
            }
#pragma unroll
            for (int mt = 0; mt < 2; mt++)
#pragma unroll
                for (int nt = 0; nt < 4; nt++)
                    mma_tf32(c[mt][nt], a[mt], b[nt]);
        }

        // fused flag partial dot from the staged A chunk
        if (doFlag) {
            int kk = cc * BK;
#pragma unroll
            for (int k = 0; k < BK; k++) {
                float hv = __uint_as_float(As[ab + fm][k]);
                fdot = fmaf(hv, sWf[kk + k][ff], fdot);
            }
        }

        if (cc + 3 < 32) {
            int st = cur + 3; if (st >= NSTG) st -= NSTG;
            stage(st, cc + 3);
        }
        CP_COMMIT();
        if (++cur == NSTG) cur = 0;
    }

    // epilogue
    int seg = c_seg[e];
#pragma unroll
    for (int mt = 0; mt < 2; mt++) {
        int r0   = wm + mt * 16 + grp;
        int tok0 = s_tok[r0];
        int tok1 = s_tok[r0 + 8];
        if (tok0 >= 0) {
            float* o = p.out + (size_t)tok0 * OUTW + seg + n0 + wn + 2 * th4;
#pragma unroll
            for (int nt = 0; nt < 4; nt++)
                *(float2*)(o + nt * 8) = make_float2(c[mt][nt][0], c[mt][nt][1]);
        }
        if (tok1 >= 0) {
            float* o = p.out + (size_t)tok1 * OUTW + seg + n0 + wn + 2 * th4;
#pragma unroll
            for (int nt = 0; nt < 4; nt++)
                *(float2*)(o + nt * 8) = make_float2(c[mt][nt][2], c[mt][nt][3]);
        }
    }

    if (doFlag) {
        int tokF = s_tok[fm];
        if (tokF >= 0)
            p.out[(size_t)tokF * OUTW + seg + 256 + f0 + ff] = fdot;
    }
}

// ---------------- host launcher ---------------------------------------------------
extern "C" void kernel_launch(void* const* d_in, const int* in_sizes, int n_in,
                              void* d_out, int out_size) {
    (void)in_sizes; (void)n_in; (void)out_size;
    // input order (setup_inputs dict order):
    // 0:A 1:X 2:Y 3:SP 4:P 5:PCH 6:PCL 7:Op 8:Val 9:fu_map
    // 10..24: (emb, W1, b1) x {alu, logic, move, flow, stack}
    // 25:alu_Wr 26:alu_Wf 27:logic_Wr 28:logic_Wf 29:move_Wo 30:flow_Wo 31:stack_Wo
    cudaFuncSetAttribute(precompute_T,
                         cudaFuncAttributeMaxDynamicSharedMemorySize, PT_SMEM);
    cudaFuncSetAttribute(gemm2_kernel,
                         cudaFuncAttributeMaxDynamicSharedMemorySize, G2_SMEM);

    PTP pt;
    HP  hp;
    for (int i = 0; i < 9; i++) hp.base[i] = (const int*)d_in[i];
    for (int e = 0; e < 5; e++) {
        pt.emb[e] = (const float*)d_in[10 + 3 * e];
        pt.W1[e]  = (const float*)d_in[11 + 3 * e];
        hp.b1[e]  = (const float*)d_in[12 + 3 * e];
    }
    CP cp;
    cp.B[0] = (const float*)d_in[25];
    cp.B[1] = (const float*)d_in[27];
    cp.B[2] = (const float*)d_in[29];
    cp.B[3] = (const float*)d_in[30];
    cp.B[4] = (const float*)d_in[31];

    G2P p2;
    p2.Wf[0] = (const float*)d_in[26];   // alu_Wf
    p2.Wf[1] = (const float*)d_in[28];   // logic_Wf
    p2.out   = (float*)d_out;

    const int* Op = (const int*)d_in[7];
    const int* fu = (const int*)d_in[9];

    int nblk = (NTOK + 5 * HDIM * 256) / 256;                 // compaction + cvtB
    compact_kernel<<<nblk, 256>>>(Op, fu, cp);                // launch 0
    precompute_T<<<dim3(4, 4, 30), 256, PT_SMEM>>>(pt);       // launch 1
    h_kernel<<<dim3(1024, 5), 256>>>(hp);                     // launch 2
    gemm2_kernel<<<dim3(4, 512, 5), 256, G2_SMEM>>>(p2);      // launch 3 (profiled)
    reset_counts<<<1, 32>>>();                                // launch 4
}

// round 16
// speedup vs baseline: 1.2303x; 1.0333x over previous
#include <cuda_runtime.h>
#include <cstdint>
#include <cstddef>

// ============================================================================
// Swarm6502 masked 5-expert MoE. R16 = R15 with gemm2 at 4 blocks/SM:
//  - NSTG=3 (48.6 KB smem), wait_group 1, stage cc+2 (R12 cadence)
//  - __launch_bounds__(256,4): 64-reg budget -> 32 warps/SM
// Pipeline: compact(+cvtB) -> precompute_T -> h -> gemm2 -> reset
// ============================================================================

#define NTOK 65536
#define HDIM 512
#define OUTW 1296
#define BK   16
#define ASP  20    // As row stride: conflict-free a-frag LDS
#define BSP  72    // Bs row stride: conflict-free b-frag LDS
#define NSTG 3

__device__ int   g_counts[5];                        // zero-init at load
__device__ int   g_lists[5][NTOK];
__device__ float g_H[(size_t)NTOK * HDIM];           // tf32-rounded hidden
__device__ float g_T[(size_t)5 * 6 * 256 * HDIM];    // lookup tables
__device__ float g_Btf[5 * HDIM * 256];              // tf32-rounded B matrices

// index source codes: 0=A 1=X 2=Y 3=SP 4=P 5=PCH 6=PCL 7=Op 8=Val 9=carry(P&1)
__constant__ int c_code[5][6] = {
    {0, 8, 9, 7, -1, -1},   // alu
    {0, 8, 9, 7, -1, -1},   // logic
    {0, 1, 2, 8, 7, -1},    // move
    {5, 6, 4, 8, 3, 7},     // flow
    {0, 1, 3, 4, 8, 7}      // stack
};
__constant__ int c_k[5]    = {4, 4, 5, 6, 6};
__constant__ int c_nout[5] = {264, 264, 256, 256, 256};
__constant__ int c_seg[5]  = {0, 264, 528, 784, 1040};

struct PTP { const float* emb[5]; const float* W1[5]; };
struct HP  { const int* base[9]; const float* b1[5]; };
struct CP  { const float* B[5]; };
struct G2P { const float* Wf[2]; float* out; };

__device__ __forceinline__ float gelu_tanh(float x) {
    float x3 = x * x * x;
    float t  = tanhf(0.7978845608028654f * (x + 0.044715f * x3));
    return 0.5f * x * (1.0f + t);
}
__device__ __forceinline__ uint32_t f2tf32(float x) {
    uint32_t r;
    asm("cvt.rna.tf32.f32 %0, %1;" : "=r"(r) : "f"(x));
    return r;
}
__device__ __forceinline__ void mma_tf32(float* c, const uint32_t* a,
                                         const uint32_t* b) {
    asm volatile(
        "mma.sync.aligned.m16n8k8.row.col.f32.tf32.tf32.f32 "
        "{%0,%1,%2,%3}, {%4,%5,%6,%7}, {%8,%9}, {%0,%1,%2,%3};"
        : "+f"(c[0]), "+f"(c[1]), "+f"(c[2]), "+f"(c[3])
        : "r"(a[0]), "r"(a[1]), "r"(a[2]), "r"(a[3]), "r"(b[0]), "r"(b[1]));
}
#define CP_ASYNC_CG(dst, src, sz) \
    asm volatile("cp.async.cg.shared.global [%0], [%1], 16, %2;" \
                 :: "r"(dst), "l"(src), "r"(sz))
#define CP_COMMIT() asm volatile("cp.async.commit_group;")
#define CP_WAIT1()  asm volatile("cp.async.wait_group 1;")

// ---------------- compact + cvtB (one launch; counts zero on entry) -------------
__global__ void compact_kernel(const int* __restrict__ Op,
                               const int* __restrict__ fu_map, CP p) {
    long gid = (long)blockIdx.x * blockDim.x + threadIdx.x;
    if (gid < NTOK) {
        int e   = fu_map[Op[gid]];
        int pos = atomicAdd(&g_counts[e], 1);
        g_lists[e][pos] = (int)gid;
    } else {
        long i = gid - NTOK;                 // 0 .. 5*131072-1
        if (i < 5L * HDIM * 256) {
            int e = (int)(i >> 17);
            int r = (int)(i & (HDIM * 256 - 1));
            g_Btf[i] = __uint_as_float(f2tf32(__ldg(p.B[e] + r)));
        }
    }
}
__global__ void reset_counts() {
    if (threadIdx.x < 5) g_counts[threadIdx.x] = 0;
}

// ---------------- precompute T[e][j] = emb_ej @ W1_ej ---------------------------
#define PT_SMEM ((64 * 65 + 64 * 128) * 4)
__global__ void __launch_bounds__(256) precompute_T(PTP p) {
    int z = blockIdx.z, e = z / 6, j = z % 6;
    if (j >= c_k[e]) return;
    int v0 = blockIdx.x * 64;
    int n0 = blockIdx.y * 128;

    extern __shared__ float smp[];
    float (*Es)[65]  = (float(*)[65])smp;
    float (*Ws)[128] = (float(*)[128])(smp + 64 * 65);
    int tid = threadIdx.x;

    {
        int r = tid >> 2, c = (tid & 3) * 16;
        const float* src = p.emb[e] + ((size_t)j * 256 + v0 + r) * 64 + c;
#pragma unroll
        for (int q = 0; q < 16; q++) Es[r][c + q] = __ldg(src + q);
    }
    {
        int r = tid >> 2, c0 = (tid & 3) * 32;
        const float4* src =
            (const float4*)(p.W1[e] + ((size_t)(j * 64 + r)) * HDIM + n0 + c0);
        float4* dst = (float4*)&Ws[r][c0];
#pragma unroll
        for (int q = 0; q < 8; q++) dst[q] = __ldg(src + q);
    }
    __syncthreads();

    float acc[4][8];
#pragma unroll
    for (int i = 0; i < 4; i++)
#pragma unroll
        for (int jj = 0; jj < 8; jj++) acc[i][jj] = 0.f;

    int tm = (tid >> 4) * 4, tn = (tid & 15) * 8;
#pragma unroll
    for (int k = 0; k < 64; k++) {
        float a[4], b[8];
#pragma unroll
        for (int i = 0; i < 4; i++) a[i] = Es[tm + i][k];
        float4 b0 = *(const float4*)&Ws[k][tn];
        float4 b1 = *(const float4*)&Ws[k][tn + 4];
        b[0] = b0.x; b[1] = b0.y; b[2] = b0.z; b[3] = b0.w;
        b[4] = b1.x; b[5] = b1.y; b[6] = b1.z; b[7] = b1.w;
#pragma unroll
        for (int i = 0; i < 4; i++)
#pragma unroll
            for (int jj = 0; jj < 8; jj++)
                acc[i][jj] = fmaf(a[i], b[jj], acc[i][jj]);
    }

    float* T = g_T + ((size_t)(e * 6 + j) * 256) * HDIM;
#pragma unroll
    for (int i = 0; i < 4; i++) {
        float* d = T + (size_t)(v0 + tm + i) * HDIM + n0 + tn;
        *(float4*)d       = make_float4(acc[i][0], acc[i][1], acc[i][2], acc[i][3]);
        *(float4*)(d + 4) = make_float4(acc[i][4], acc[i][5], acc[i][6], acc[i][7]);
    }
}

// ---------------- h v2: smem-staged indices -> independent gathers ---------------
__global__ void __launch_bounds__(256) h_kernel(HP p) {
    int e  = blockIdx.y;
    int C  = g_counts[e];
    int m0 = blockIdx.x * 64;
    if (m0 >= C) return;

    __shared__ int s_tok[64];
    __shared__ int s_idx[6][64];

    int tid = threadIdx.x;
    int kc  = c_k[e];
    if (tid < 64) {
        int m = m0 + tid;
        s_tok[tid] = (m < C) ? g_lists[e][m] : -1;
    }
    __syncthreads();
    for (int u = tid; u < kc * 64; u += 256) {
        int j = u >> 6, m = u & 63;
        int tok = s_tok[m];
        int idx = 0;
        if (tok >= 0) {
            int code = c_code[e][j];
            idx = (code == 9) ? (__ldg(p.base[4] + tok) & 1)
                              : __ldg(p.base[code] + tok);
        }
        s_idx[j][m] = idx;
    }
    __syncthreads();

    int g = tid >> 7, t = tid & 127;
    float4 bias = __ldg((const float4*)p.b1[e] + t);
    const float* Tb = g_T + ((size_t)(e * 6) << 17);

    for (int lm = g * 32; lm < g * 32 + 32; lm += 2) {
        int tok0 = s_tok[lm], tok1 = s_tok[lm + 1];
        if (tok0 < 0) continue;
        float4 a0 = bias, a1 = bias;
        for (int j = 0; j < kc; j++) {
            float4 v0 = ((const float4*)(
                Tb + (((size_t)j * 256 + s_idx[j][lm]) << 9)))[t];
            a0.x += v0.x; a0.y += v0.y; a0.z += v0.z; a0.w += v0.w;
            if (tok1 >= 0) {
                float4 v1 = ((const float4*)(
                    Tb + (((size_t)j * 256 + s_idx[j][lm + 1]) << 9)))[t];
                a1.x += v1.x; a1.y += v1.y; a1.z += v1.z; a1.w += v1.w;
            }
        }
        float4 o0;
        o0.x = __uint_as_float(f2tf32(gelu_tanh(a0.x)));
        o0.y = __uint_as_float(f2tf32(gelu_tanh(a0.y)));
        o0.z = __uint_as_float(f2tf32(gelu_tanh(a0.z)));
        o0.w = __uint_as_float(f2tf32(gelu_tanh(a0.w)));
        ((float4*)(g_H + ((size_t)tok0 << 9)))[t] = o0;
        if (tok1 >= 0) {
            float4 o1;
            o1.x = __uint_as_float(f2tf32(gelu_tanh(a1.x)));
            o1.y = __uint_as_float(f2tf32(gelu_tanh(a1.y)));
            o1.z = __uint_as_float(f2tf32(gelu_tanh(a1.z)));
            o1.w = __uint_as_float(f2tf32(gelu_tanh(a1.w)));
            ((float4*)(g_H + ((size_t)tok1 << 9)))[t] = o1;
        }
    }
}

// ---------------- gemm2 v9: NSTG=3, 4 blocks/SM, fused flags ---------------------
// (C x 512) @ (512 x 256). BM=128, BN=64, BK=16, 32 chunks, 3 stages, 8 warps.
// warp tile 32x32. grid (4, 512, 5): n0 inner -> A tile L2-shared by 4 blocks.
#define SWF_OFF (NSTG * (128 * ASP + BK * BSP))        // word offset of sWf
#define G2_SMEM ((SWF_OFF + 512 * 2) * 4)
__global__ void __launch_bounds__(256, 4) gemm2_kernel(G2P p) {
    int e  = blockIdx.z;
    int C  = g_counts[e];
    int m0 = blockIdx.y * 128;
    if (m0 >= C) return;
    int n0 = blockIdx.x * 64;

    extern __shared__ uint32_t smg[];
    uint32_t (*As)[ASP] = (uint32_t(*)[ASP])smg;                      // [NSTG*128][ASP]
    uint32_t (*Bs)[BSP] = (uint32_t(*)[BSP])(smg + NSTG * 128 * ASP); // [NSTG*BK][BSP]
    float (*sWf)[2] = (float(*)[2])(smg + SWF_OFF);                   // [512][2]
    __shared__ int s_tok[128];

    int tid = threadIdx.x;
    if (tid < 128) {
        int m = m0 + tid;
        s_tok[tid] = (m < C) ? g_lists[e][m] : -1;
    }
    bool doFlag = (e < 2);
    int f0 = blockIdx.x * 2;
    if (doFlag) {
        const float* Wf = p.Wf[e];
        for (int u = tid; u < 512; u += 256) {
            sWf[u][0] = __ldg(Wf + u * 8 + f0);
            sWf[u][1] = __ldg(Wf + u * 8 + f0 + 1);
        }
    }
    __syncthreads();

    // zero-fill complement, distributed across the 4 n-blocks of this m-tile
    {
        int s4 = c_seg[e] >> 2;
        int e4 = (c_seg[e] + c_nout[e]) >> 2;
        float4* out4 = (float4*)p.out;
        float4 z = make_float4(0.f, 0.f, 0.f, 0.f);
        for (int u = tid + (int)blockIdx.x * 256; u < 128 * (OUTW / 4);
             u += 1024) {
            int m = u / (OUTW / 4);
            int f = u - m * (OUTW / 4);
            if (f >= s4 && f < e4) continue;
            int tok = s_tok[m];
            if (tok < 0) continue;
            out4[(size_t)tok * (OUTW / 4) + f] = z;
        }
    }

    // ---- staging assignments (fixed per thread) ----
    int ar0 = tid >> 2;              // rows 0..63
    int ar1 = 64 + ar0;              // rows 64..127
    int akq = (tid & 3) * 4;         // k-quad within chunk
    int tokA0 = s_tok[ar0], tokA1 = s_tok[ar1];
    const float* srcA0 = g_H + ((size_t)(tokA0 < 0 ? 0 : tokA0) << 9) + akq;
    const float* srcA1 = g_H + ((size_t)(tokA1 < 0 ? 0 : tokA1) << 9) + akq;
    int szA0 = (tokA0 < 0) ? 0 : 16;
    int szA1 = (tokA1 < 0) ? 0 : 16;
    int bk = tid >> 4;               // 0..15 (B k-row)
    int bn = (tid & 15) * 4;         // 0..60
    const float* __restrict__ Bg = g_Btf + ((size_t)e * HDIM * 256);

    uint32_t sbase = (uint32_t)__cvta_generic_to_shared(smg);
    const uint32_t BOFF = NSTG * 128 * ASP * 4;   // byte offset of Bs

    auto stage = [&](int st, int cc) {
        int kk = cc * BK;
        uint32_t dA0 = sbase + ((st * 128 + ar0) * ASP + akq) * 4;
        uint32_t dA1 = sbase + ((st * 128 + ar1) * ASP + akq) * 4;
        CP_ASYNC_CG(dA0, srcA0 + kk, szA0);
        CP_ASYNC_CG(dA1, srcA1 + kk, szA1);
        uint32_t dB = sbase + BOFF + ((st * BK + bk) * BSP + bn) * 4;
        CP_ASYNC_CG(dB, Bg + (size_t)(kk + bk) * 256 + n0 + bn, 16);
    };

    int lane = tid & 31, wrp = tid >> 5;
    int wm = (wrp & 3) * 32;
    int wn = (wrp >> 2) * 32;
    int grp = lane >> 2, th4 = lane & 3;

    // flag assignment: 1 (token, flag) pair per thread
    int fm = tid >> 1;               // token row 0..127
    int ff = tid & 1;                // 0/1 -> flag col f0+ff
    float fdot = 0.f;

    float c[2][4][4];
#pragma unroll
    for (int mt = 0; mt < 2; mt++)
#pragma unroll
        for (int nt = 0; nt < 4; nt++)
#pragma unroll
            for (int i = 0; i < 4; i++) c[mt][nt][i] = 0.f;

    stage(0, 0); CP_COMMIT();
    stage(1, 1); CP_COMMIT();

    int cur = 0;
    for (int cc = 0; cc < 32; cc++) {
        CP_WAIT1();
        __syncthreads();

        int ab = cur * 128;
        int bb = cur * BK;
#pragma unroll
        for (int k8 = 0; k8 < BK; k8 += 8) {
            int kb = k8 + th4;
            uint32_t a[2][4], b[4][2];
#pragma unroll
            for (int mt = 0; mt < 2; mt++) {
                int mb = ab + wm + mt * 16;
                a[mt][0] = As[mb + grp][kb];
                a[mt][1] = As[mb + 8 + grp][kb];
                a[mt][2] = As[mb + grp][kb + 4];
                a[mt][3] = As[mb + 8 + grp][kb + 4];
            }
#pragma unroll
            for (int nt = 0; nt < 4; nt++) {
                b[nt][0] = Bs[bb + kb][wn + nt * 8 + grp];
                b[nt][1] = Bs[bb + kb + 4][wn + nt * 8 + grp];
            }
#pragma unroll
            for (int mt = 0; mt < 2; mt++)
#pragma unroll
                for (int nt = 0; nt < 4; nt++)
                    mma_tf32(c[mt][nt], a[mt], b[nt]);
        }

        // fused flag partial dot from the staged A chunk
        if (doFlag) {
            int kk = cc * BK;
#pragma unroll
            for (int k = 0; k < BK; k++) {
                float hv = __uint_as_float(As[ab + fm][k]);
                fdot = fmaf(hv, sWf[kk + k][ff], fdot);
            }
        }

        if (cc + 2 < 32) {
            int st = cur + 2; if (st >= NSTG) st -= NSTG;
            stage(st, cc + 2);
        }
        CP_COMMIT();
        if (++cur == NSTG) cur = 0;
    }

    // epilogue
    int seg = c_seg[e];
#pragma unroll
    for (int mt = 0; mt < 2; mt++) {
        int r0   = wm + mt * 16 + grp;
        int tok0 = s_tok[r0];
        int tok1 = s_tok[r0 + 8];
        if (tok0 >= 0) {
            float* o = p.out + (size_t)tok0 * OUTW + seg + n0 + wn + 2 * th4;
#pragma unroll
            for (int nt = 0; nt < 4; nt++)
                *(float2*)(o + nt * 8) = make_float2(c[mt][nt][0], c[mt][nt][1]);
        }
        if (tok1 >= 0) {
            float* o = p.out + (size_t)tok1 * OUTW + seg + n0 + wn + 2 * th4;
#pragma unroll
            for (int nt = 0; nt < 4; nt++)
                *(float2*)(o + nt * 8) = make_float2(c[mt][nt][2], c[mt][nt][3]);
        }
    }

    if (doFlag) {
        int tokF = s_tok[fm];
        if (tokF >= 0)
            p.out[(size_t)tokF * OUTW + seg + 256 + f0 + ff] = fdot;
    }
}

// ---------------- host launcher ---------------------------------------------------
extern "C" void kernel_launch(void* const* d_in, const int* in_sizes, int n_in,
                              void* d_out, int out_size) {
    (void)in_sizes; (void)n_in; (void)out_size;
    // input order (setup_inputs dict order):
    // 0:A 1:X 2:Y 3:SP 4:P 5:PCH 6:PCL 7:Op 8:Val 9:fu_map
    // 10..24: (emb, W1, b1) x {alu, logic, move, flow, stack}
    // 25:alu_Wr 26:alu_Wf 27:logic_Wr 28:logic_Wf 29:move_Wo 30:flow_Wo 31:stack_Wo
    cudaFuncSetAttribute(precompute_T,
                         cudaFuncAttributeMaxDynamicSharedMemorySize, PT_SMEM);
    cudaFuncSetAttribute(gemm2_kernel,
                         cudaFuncAttributeMaxDynamicSharedMemorySize, G2_SMEM);

    PTP pt;
    HP  hp;
    for (int i = 0; i < 9; i++) hp.base[i] = (const int*)d_in[i];
    for (int e = 0; e < 5; e++) {
        pt.emb[e] = (const float*)d_in[10 + 3 * e];
        pt.W1[e]  = (const float*)d_in[11 + 3 * e];
        hp.b1[e]  = (const float*)d_in[12 + 3 * e];
    }
    CP cp;
    cp.B[0] = (const float*)d_in[25];
    cp.B[1] = (const float*)d_in[27];
    cp.B[2] = (const float*)d_in[29];
    cp.B[3] = (const float*)d_in[30];
    cp.B[4] = (const float*)d_in[31];

    G2P p2;
    p2.Wf[0] = (const float*)d_in[26];   // alu_Wf
    p2.Wf[1] = (const float*)d_in[28];   // logic_Wf
    p2.out   = (float*)d_out;

    const int* Op = (const int*)d_in[7];
    const int* fu = (const int*)d_in[9];

    int nblk = (NTOK + 5 * HDIM * 256) / 256;                 // compaction + cvtB
    compact_kernel<<<nblk, 256>>>(Op, fu, cp);                // launch 0
    precompute_T<<<dim3(4, 4, 30), 256, PT_SMEM>>>(pt);       // launch 1
    h_kernel<<<dim3(1024, 5), 256>>>(hp);                     // launch 2
    gemm2_kernel<<<dim3(4, 512, 5), 256, G2_SMEM>>>(p2);      // launch 3 (profiled)
    reset_counts<<<1, 32>>>();                                // launch 4
}